// round 4
// baseline (speedup 1.0000x reference)
#include <cuda_runtime.h>
#include <cstdint>

// PPEG: out[b, 0, c]   = x[b, 0, c]                       (cls token)
//       out[b, 1+p, c] = combined 7x7 depthwise conv of the 64x64 map
// Combined weights: w_eff = w7 + pad(w5) + pad(w3) + identity@center
// Combined bias:    b7 + b5 + b3

#define CH   512
#define HW   64
#define NTOK 4097

// conv tiling
#define TX   16            // tile width  (pixels)
#define TY   8             // tile height (pixels)
#define IW   22            // input tile width  = TX+6
#define IH   14            // input tile height = TY+6
#define CG   64            // channels per block

__device__ float g_weff[49 * CH];   // [tap][channel]
__device__ float g_bsum[CH];

// packed f32x2 FMA (sm_103a FFMA2 — only reachable via PTX)
__device__ __forceinline__ unsigned long long ffma2(unsigned long long a,
                                                    unsigned long long b,
                                                    unsigned long long c) {
    unsigned long long d;
    asm("fma.rn.f32x2 %0, %1, %2, %3;" : "=l"(d) : "l"(a), "l"(b), "l"(c));
    return d;
}

__device__ __forceinline__ uint32_t smem_u32(const void* p) {
    uint32_t a;
    asm("{ .reg .u64 t; cvta.to.shared.u64 t, %1; cvt.u32.u64 %0, t; }"
        : "=r"(a) : "l"(p));
    return a;
}

// cp.async 16B with zero-fill when src_sz == 0
__device__ __forceinline__ void cpa16(uint32_t dst, const void* src, int src_sz) {
    asm volatile("cp.async.ca.shared.global [%0], [%1], 16, %2;"
                 :: "r"(dst), "l"(src), "r"(src_sz) : "memory");
}

// ---------------------------------------------------------------------------
// Kernel 1: weight fold + bias + cls copy, one launch.
__global__ void ppeg_prep(const float* __restrict__ w7, const float* __restrict__ b7,
                          const float* __restrict__ w5, const float* __restrict__ b5,
                          const float* __restrict__ w3, const float* __restrict__ b3,
                          const float* __restrict__ x, float* __restrict__ out) {
    const int bid = blockIdx.x;
    const int tid = threadIdx.x;
    if (bid < 98) {
        const int i = bid * 256 + tid;        // 0 .. 25087 = 512*49
        const int c = i / 49;
        const int t = i % 49;
        const int ky = t / 7, kx = t % 7;
        float v = w7[c * 49 + t];
        if (ky >= 1 && ky <= 5 && kx >= 1 && kx <= 5)
            v += w5[c * 25 + (ky - 1) * 5 + (kx - 1)];
        if (ky >= 2 && ky <= 4 && kx >= 2 && kx <= 4)
            v += w3[c * 9 + (ky - 2) * 3 + (kx - 2)];
        if (t == 24) v += 1.0f;               // identity (residual) term
        g_weff[t * CH + c] = v;
    } else if (bid < 100) {
        const int c = (bid - 98) * 256 + tid;
        g_bsum[c] = b7[c] + b5[c] + b3[c];
    } else {
        const int j = (bid - 100) * 256 + tid;   // cls: 16*512 floats
        const int b = j >> 9;
        const int cc = j & 511;
        const size_t off = (size_t)b * NTOK * CH + cc;
        out[off] = x[off];
    }
}

// ---------------------------------------------------------------------------
// Kernel 2: combined 7x7 depthwise conv, SMEM-staged input tile.
//   block: 16x8 px tile, 64 channels, 256 threads (8 warps of 8x2 px)
//   smem : input 14x22x64 f32 (cp.async, zero-filled halo) + weights + bias
//   inner loop: pure LDS + FFMA2 — no global loads, no predication.
extern __shared__ float s_dyn[];
__global__ void __launch_bounds__(256, 2)
ppeg_conv(const float* __restrict__ x, float* __restrict__ out) {
    float* s_in = s_dyn;                       // IH*IW*CG = 19712 floats
    float* sw   = s_dyn + IH * IW * CG;        // 49*CG    =  3136 floats
    float* sb   = sw + 49 * CG;                // CG

    const int tid  = threadIdx.x;
    const int lane = tid & 31;
    const int warp = tid >> 5;                 // 0..7
    const int wx = warp & 1;                   // 0..1
    const int wy = warp >> 1;                  // 0..3
    const int bxp = blockIdx.x * TX;           // tile origin (pixels)
    const int byp = blockIdx.y * TY;
    const int b  = blockIdx.z >> 3;
    const int cg = blockIdx.z & 7;
    const int cb = cg * CG;

    // ---- stage weights + bias (plain loads; small) ----
    for (int i = tid; i < 49 * CG; i += 256) {
        const int t  = i >> 6;
        const int cc = i & 63;
        sw[i] = g_weff[t * CH + cb + cc];
    }
    if (tid < CG) sb[tid] = g_bsum[cb + tid];

    // ---- stage input tile via cp.async (16B chunks, zero-fill halo) ----
    const float* xb = x + ((size_t)b * NTOK + 1) * CH + cb;
    const uint32_t s_in_u = smem_u32(s_in);
    // chunk layout: c4 (16 chunks of 4ch) fastest, then col j (22), then row r (14)
    #pragma unroll
    for (int it = 0; it < 20; ++it) {
        const int idx = it * 256 + tid;
        if (idx < IH * IW * 16) {
            const int c4 = idx & 15;
            const int rest = idx >> 4;
            const int j = rest % IW;
            const int r = rest / IW;
            const int iy = byp - 3 + r;
            const int ix = bxp - 3 + j;
            const bool ok = ((unsigned)iy < (unsigned)HW) & ((unsigned)ix < (unsigned)HW);
            const int iyc = ok ? iy : 0;
            const int ixc = ok ? ix : 0;
            const float* g = xb + ((size_t)iyc * HW + ixc) * CH + c4 * 4;
            const uint32_t s = s_in_u + (uint32_t)(((r * IW + j) * CG + c4 * 4) * 4);
            cpa16(s, g, ok ? 16 : 0);
        }
    }
    asm volatile("cp.async.commit_group;" ::: "memory");
    asm volatile("cp.async.wait_group 0;" ::: "memory");
    __syncthreads();

    // ---- compute: thread = 8x2 pixels at (wx*8, wy*2) in the tile ----
    const int x0l = wx * 8;                    // local output col base
    const int y0l = wy * 2;                    // local output row base
    const float* swp = &sw[lane * 2];

    const unsigned long long bias =
        *reinterpret_cast<const unsigned long long*>(&sb[lane * 2]);
    unsigned long long acc[2][8];
    #pragma unroll
    for (int ry = 0; ry < 2; ++ry)
        #pragma unroll
        for (int rx = 0; rx < 8; ++rx)
            acc[ry][rx] = bias;

    // input rows needed: y0l .. y0l+7 (local, halo-shifted: row r maps to input row y0l+r)
    #pragma unroll
    for (int r = 0; r < 8; ++r) {
        const float* rowp = &s_in[((y0l + r) * IW + x0l) * CG + lane * 2];
        unsigned long long rw[14];
        #pragma unroll
        for (int i = 0; i < 14; ++i)
            rw[i] = *reinterpret_cast<const unsigned long long*>(&rowp[i * CG]);

        #pragma unroll
        for (int ky = 0; ky < 7; ++ky) {
            const int ry = r - ky;             // compile-time after unroll
            if (ry == 0 || ry == 1) {
                #pragma unroll
                for (int kx = 0; kx < 7; ++kx) {
                    const unsigned long long wk =
                        *reinterpret_cast<const unsigned long long*>(
                            &swp[(ky * 7 + kx) * CG]);
                    #pragma unroll
                    for (int rx = 0; rx < 8; ++rx)
                        acc[ry][rx] = ffma2(rw[rx + kx], wk, acc[ry][rx]);
                }
            }
        }
    }

    // ---- store ----
    float* ob = out + ((size_t)b * NTOK + 1) * CH + cb + lane * 2;
    #pragma unroll
    for (int ry = 0; ry < 2; ++ry)
        #pragma unroll
        for (int rx = 0; rx < 8; ++rx) {
            const size_t p = (size_t)(byp + y0l + ry) * HW + (bxp + x0l + rx);
            *reinterpret_cast<unsigned long long*>(&ob[p * CH]) = acc[ry][rx];
        }
}

// ---------------------------------------------------------------------------
extern "C" void kernel_launch(void* const* d_in, const int* in_sizes, int n_in,
                              void* d_out, int out_size) {
    const float* x  = (const float*)d_in[0];
    const float* w7 = (const float*)d_in[1];
    const float* b7 = (const float*)d_in[2];
    const float* w5 = (const float*)d_in[3];
    const float* b5 = (const float*)d_in[4];
    const float* w3 = (const float*)d_in[5];
    const float* b3 = (const float*)d_in[6];
    float* out = (float*)d_out;

    const int smem = (IH * IW * CG + 49 * CG + CG) * (int)sizeof(float); // 91,904 B
    static bool configured = false;
    if (!configured) {
        cudaFuncSetAttribute(ppeg_conv, cudaFuncAttributeMaxDynamicSharedMemorySize, smem);
        configured = true;
    }

    ppeg_prep<<<132, 256>>>(w7, b7, w5, b5, w3, b3, x, out);
    dim3 grid(HW / TX, HW / TY, 16 * 8);       // (4, 8, 128)
    ppeg_conv<<<grid, 256, smem>>>(x, out);
}

// round 5
// speedup vs baseline: 1.0237x; 1.0237x over previous
#include <cuda_runtime.h>
#include <cstdint>

// PPEG: out[b, 0, c]   = x[b, 0, c]                       (cls token)
//       out[b, 1+p, c] = combined 7x7 depthwise conv of the 64x64 map
// Combined weights: w_eff = w7 + pad(w5) + pad(w3) + identity@center
// Combined bias:    b7 + b5 + b3

#define CH   512
#define HW   64
#define NTOK 4097

// conv tiling
#define TX   16            // tile width  (pixels)
#define TY   8             // tile height (pixels)
#define IW   22            // input tile width  = TX+6
#define IH   14            // input tile height = TY+6
#define CG   64            // channels per block

typedef unsigned long long ULL;

__device__ float g_weff[49 * CH];   // [tap][channel]
__device__ float g_bsum[CH];

// packed f32x2 FMA (sm_103a FFMA2 — only reachable via PTX)
__device__ __forceinline__ ULL ffma2(ULL a, ULL b, ULL c) {
    ULL d;
    asm("fma.rn.f32x2 %0, %1, %2, %3;" : "=l"(d) : "l"(a), "l"(b), "l"(c));
    return d;
}

__device__ __forceinline__ uint32_t smem_u32(const void* p) {
    uint32_t a;
    asm("{ .reg .u64 t; cvta.to.shared.u64 t, %1; cvt.u32.u64 %0, t; }"
        : "=r"(a) : "l"(p));
    return a;
}

// cp.async 16B with zero-fill when src_sz == 0
__device__ __forceinline__ void cpa16(uint32_t dst, const void* src, int src_sz) {
    asm volatile("cp.async.ca.shared.global [%0], [%1], 16, %2;"
                 :: "r"(dst), "l"(src), "r"(src_sz) : "memory");
}

// ---------------------------------------------------------------------------
// Kernel 1: weight fold + bias + cls copy, one launch.
__global__ void ppeg_prep(const float* __restrict__ w7, const float* __restrict__ b7,
                          const float* __restrict__ w5, const float* __restrict__ b5,
                          const float* __restrict__ w3, const float* __restrict__ b3,
                          const float* __restrict__ x, float* __restrict__ out) {
    const int bid = blockIdx.x;
    const int tid = threadIdx.x;
    if (bid < 98) {
        const int i = bid * 256 + tid;        // 0 .. 25087 = 512*49
        const int c = i / 49;
        const int t = i % 49;
        const int ky = t / 7, kx = t % 7;
        float v = w7[c * 49 + t];
        if (ky >= 1 && ky <= 5 && kx >= 1 && kx <= 5)
            v += w5[c * 25 + (ky - 1) * 5 + (kx - 1)];
        if (ky >= 2 && ky <= 4 && kx >= 2 && kx <= 4)
            v += w3[c * 9 + (ky - 2) * 3 + (kx - 2)];
        if (t == 24) v += 1.0f;               // identity (residual) term
        g_weff[t * CH + c] = v;
    } else if (bid < 100) {
        const int c = (bid - 98) * 256 + tid;
        g_bsum[c] = b7[c] + b5[c] + b3[c];
    } else {
        const int j = (bid - 100) * 256 + tid;   // cls: 16*512 floats
        const int b = j >> 9;
        const int cc = j & 511;
        const size_t off = (size_t)b * NTOK * CH + cc;
        out[off] = x[off];
    }
}

// ---------------------------------------------------------------------------
// Kernel 2: combined 7x7 depthwise conv, SMEM-staged input tile.
//   block: 16x8 px tile, 64 channels, 256 threads (8 warps of 8x2 px)
//   staging: div-free cp.async mapping, zero-filled halo
//   compute: riy-major; weight rows slide through regs (49 weight LDS total);
//            inner loop is LDS + FFMA2 only.
extern __shared__ float s_dyn[];
__global__ void __launch_bounds__(256, 2)
ppeg_conv(const float* __restrict__ x, float* __restrict__ out) {
    float* s_in = s_dyn;                       // IH*IW*CG = 19712 floats
    float* sw   = s_dyn + IH * IW * CG;        // 49*CG    =  3136 floats
    float* sb   = sw + 49 * CG;                // CG

    const int tid  = threadIdx.x;
    const int lane = tid & 31;
    const int warp = tid >> 5;                 // 0..7
    const int wx = warp & 1;                   // 0..1
    const int wy = warp >> 1;                  // 0..3
    const int bxp = blockIdx.x * TX;           // tile origin (pixels)
    const int byp = blockIdx.y * TY;
    const int b  = blockIdx.z >> 3;
    const int cg = blockIdx.z & 7;
    const int cb = cg * CG;

    // ---- stage weights + bias ----
    for (int i = tid; i < 49 * CG; i += 256) {
        const int t  = i >> 6;
        const int cc = i & 63;
        sw[i] = g_weff[t * CH + cb + cc];
    }
    if (tid < CG) sb[tid] = g_bsum[cb + tid];

    // ---- stage input tile: div-free mapping ----
    // thread -> (c4 = tid&15 : which 16B channel chunk, j0 = tid>>4 : column)
    const float* xb = x + ((size_t)b * NTOK + 1) * CH + cb;
    const uint32_t s_in_u = smem_u32(s_in);
    {
        const int c4 = tid & 15;
        const int j0 = tid >> 4;               // 0..15
        #pragma unroll
        for (int r = 0; r < IH; ++r) {
            const int iy = byp - 3 + r;
            const bool yok = ((unsigned)iy < (unsigned)HW);
            #pragma unroll
            for (int jj = 0; jj < 2; ++jj) {
                const int j = j0 + jj * 16;
                if (jj == 0 || j0 < IW - 16) {     // j < 22
                    const int ix = bxp - 3 + j;
                    const bool ok = yok && ((unsigned)ix < (unsigned)HW);
                    const int iyc = ok ? iy : 0;
                    const int ixc = ok ? ix : 0;
                    const float* g = xb + ((size_t)iyc * HW + ixc) * CH + c4 * 4;
                    const uint32_t s = s_in_u +
                        (uint32_t)(((r * IW + j) * CG + c4 * 4) * 4);
                    cpa16(s, g, ok ? 16 : 0);
                }
            }
        }
    }
    asm volatile("cp.async.commit_group;" ::: "memory");
    asm volatile("cp.async.wait_group 0;" ::: "memory");
    __syncthreads();

    // ---- compute: thread = 8x2 pixels at (wx*8, wy*2) in the tile ----
    const int x0l = wx * 8;
    const int y0l = wy * 2;
    const float* swp  = &sw[lane * 2];
    const float* winp = &s_in[(y0l * IW + x0l) * CG + lane * 2];

    const ULL bias = *reinterpret_cast<const ULL*>(&sb[lane * 2]);
    ULL acc[2][8];
    #pragma unroll
    for (int ry = 0; ry < 2; ++ry)
        #pragma unroll
        for (int rx = 0; rx < 8; ++rx)
            acc[ry][rx] = bias;

    ULL wk[2][7];                              // sliding weight rows

    #pragma unroll
    for (int riy = 0; riy < 8; ++riy) {
        const int cur = riy & 1;
        const int prv = cur ^ 1;

        if (riy < 7) {                         // load weight row ky = riy once
            #pragma unroll
            for (int kx = 0; kx < 7; ++kx)
                wk[cur][kx] = *reinterpret_cast<const ULL*>(
                    &swp[(riy * 7 + kx) * CG]);
        }

        const float* rowp = winp + riy * (IW * CG);
        ULL rw[14];
        #pragma unroll
        for (int i = 0; i < 14; ++i)
            rw[i] = *reinterpret_cast<const ULL*>(&rowp[i * CG]);

        if (riy <= 6) {                        // ry=0 uses ky = riy
            #pragma unroll
            for (int kx = 0; kx < 7; ++kx)
                #pragma unroll
                for (int rx = 0; rx < 8; ++rx)
                    acc[0][rx] = ffma2(rw[rx + kx], wk[cur][kx], acc[0][rx]);
        }
        if (riy >= 1) {                        // ry=1 uses ky = riy-1
            #pragma unroll
            for (int kx = 0; kx < 7; ++kx)
                #pragma unroll
                for (int rx = 0; rx < 8; ++rx)
                    acc[1][rx] = ffma2(rw[rx + kx], wk[prv][kx], acc[1][rx]);
        }
    }

    // ---- store ----
    float* ob = out + ((size_t)b * NTOK + 1) * CH + cb + lane * 2;
    #pragma unroll
    for (int ry = 0; ry < 2; ++ry)
        #pragma unroll
        for (int rx = 0; rx < 8; ++rx) {
            const size_t p = (size_t)(byp + y0l + ry) * HW + (bxp + x0l + rx);
            *reinterpret_cast<ULL*>(&ob[p * CH]) = acc[ry][rx];
        }
}

// ---------------------------------------------------------------------------
extern "C" void kernel_launch(void* const* d_in, const int* in_sizes, int n_in,
                              void* d_out, int out_size) {
    const float* x  = (const float*)d_in[0];
    const float* w7 = (const float*)d_in[1];
    const float* b7 = (const float*)d_in[2];
    const float* w5 = (const float*)d_in[3];
    const float* b5 = (const float*)d_in[4];
    const float* w3 = (const float*)d_in[5];
    const float* b3 = (const float*)d_in[6];
    float* out = (float*)d_out;

    const int smem = (IH * IW * CG + 49 * CG + CG) * (int)sizeof(float); // 91,712 B
    static bool configured = false;
    if (!configured) {
        cudaFuncSetAttribute(ppeg_conv, cudaFuncAttributeMaxDynamicSharedMemorySize, smem);
        configured = true;
    }

    ppeg_prep<<<132, 256>>>(w7, b7, w5, b5, w3, b3, x, out);
    dim3 grid(HW / TX, HW / TY, 16 * 8);       // (4, 8, 128)
    ppeg_conv<<<grid, 256, smem>>>(x, out);
}